// round 5
// baseline (speedup 1.0000x reference)
#include <cuda_runtime.h>
#include <cstdint>

#define BB   4
#define SQL  4096
#define SKVL 4096
#define DINL 256
#define DKL  256

// Scratch for projected Q, K, V
__device__ float g_Q[(size_t)BB * SQL  * DKL];
__device__ float g_K[(size_t)BB * SKVL * DKL];
__device__ float g_V[(size_t)BB * SKVL * DKL];

// ---------------------------------------------------------------------------
// cp.async helpers (16B, GMEM -> SMEM, no register staging)
// ---------------------------------------------------------------------------
__device__ __forceinline__ void cp16(void* dst_smem, const void* src) {
    uint32_t d = (uint32_t)__cvta_generic_to_shared(dst_smem);
    asm volatile("cp.async.cg.shared.global [%0], [%1], 16;\n" :: "r"(d), "l"(src));
}
#define CP_COMMIT() asm volatile("cp.async.commit_group;\n" ::: "memory")
#define CP_WAIT1()  asm volatile("cp.async.wait_group 1;\n"  ::: "memory")

// ---------------------------------------------------------------------------
// Projection GEMM: C[M][256] = A[M][256] @ W[256][256] + bias   (unchanged)
// ---------------------------------------------------------------------------
__global__ __launch_bounds__(256) void proj_gemm(const float* __restrict__ A,
                                                 const float* __restrict__ W,
                                                 const float* __restrict__ bias,
                                                 float* __restrict__ C) {
    __shared__ float sA[64][36];
    __shared__ float sW[32][68];
    const int m0 = blockIdx.x * 64;
    const int n0 = blockIdx.y * 64;
    const int tid = threadIdx.x;
    const int tx = tid & 15, ty = tid >> 4;

    float acc[4][4] = {};

    for (int k0 = 0; k0 < DINL; k0 += 32) {
        __syncthreads();
#pragma unroll
        for (int r = 0; r < 2; r++) {
            int s = tid + r * 256;
            int row = s >> 3, seg = s & 7;
            *(float4*)&sA[row][seg * 4] =
                *(const float4*)(A + (size_t)(m0 + row) * DINL + k0 + seg * 4);
        }
#pragma unroll
        for (int r = 0; r < 2; r++) {
            int s = tid + r * 256;
            int row = s >> 4, seg = s & 15;
            *(float4*)&sW[row][seg * 4] =
                *(const float4*)(W + (size_t)(k0 + row) * DKL + n0 + seg * 4);
        }
        __syncthreads();
#pragma unroll
        for (int kk = 0; kk < 32; kk += 4) {
            float4 w0 = *(const float4*)&sW[kk + 0][tx * 4];
            float4 w1 = *(const float4*)&sW[kk + 1][tx * 4];
            float4 w2 = *(const float4*)&sW[kk + 2][tx * 4];
            float4 w3 = *(const float4*)&sW[kk + 3][tx * 4];
#pragma unroll
            for (int i = 0; i < 4; i++) {
                float4 a = *(const float4*)&sA[ty * 4 + i][kk];
                acc[i][0] += a.x * w0.x + a.y * w1.x + a.z * w2.x + a.w * w3.x;
                acc[i][1] += a.x * w0.y + a.y * w1.y + a.z * w2.y + a.w * w3.y;
                acc[i][2] += a.x * w0.z + a.y * w1.z + a.z * w2.z + a.w * w3.z;
                acc[i][3] += a.x * w0.w + a.y * w1.w + a.z * w2.w + a.w * w3.w;
            }
        }
    }
    float4 bv = *(const float4*)(bias + n0 + tx * 4);
#pragma unroll
    for (int i = 0; i < 4; i++) {
        float4 o = make_float4(acc[i][0] + bv.x, acc[i][1] + bv.y,
                               acc[i][2] + bv.z, acc[i][3] + bv.w);
        *(float4*)(C + (size_t)(m0 + ty * 4 + i) * DKL + n0 + tx * 4) = o;
    }
}

// ---------------------------------------------------------------------------
// Flash attention, fp32, retiled for low LDS/FMA ratio.
// BM=64 q-rows/CTA, BN=128 kv/tile, 256 threads.
// Thread map (both phases): tyv = tid>>5 (8 groups -> rows tyv*8+r),
//                           txv = tid&31 (S cols txv+32c, O cols txv*4 (+128)).
// S-phase: per-thread 8x4 tile, Q/K streamed in d-chunks of 32 via cp.async
//          double buffer.  1.5 B/FMA.
// PV-phase: per-thread 8x8 O tile, P row-major in smem (broadcast reads),
//          V streamed in 8-row chunks via cp.async double buffer. 1.0 B/FMA.
// m/l softmax state in smem (rows exclusive per warp -> no races).
// Smem = 106,240 B -> 2 CTAs/SM.
// ---------------------------------------------------------------------------
#define QPCH 36     // Q chunk pitch (32+4)
#define KPCH 36     // K chunk pitch
#define VPCH 260    // V chunk pitch (256+4)
#define PPCH 132    // P pitch (128+4)

#define SQ_OFF  0                    // [2][64*36]   = 4608
#define SK_OFF  4608                 // [2][128*36]  = 9216
#define SV_OFF  13824                // [2][8*260]   = 4160
#define SP_OFF  17984                // [64][132]    = 8448
#define SMM_OFF 26432                // [64]
#define SLL_OFF 26496                // [64]
#define SMEM_FLOATS 26560

__device__ __forceinline__ void issue_qk(float* sQb, float* sKb,
                                         const float* Qg, const float* Kt,
                                         int dc, int tid) {
#pragma unroll
    for (int r = 0; r < 2; r++) {               // Q: 64 rows x 8 f4
        int s = tid + r * 256;
        int row = s >> 3, seg = s & 7;
        cp16(sQb + row * QPCH + seg * 4,
             Qg + (size_t)row * DKL + dc * 32 + seg * 4);
    }
#pragma unroll
    for (int r = 0; r < 4; r++) {               // K: 128 rows x 8 f4
        int s = tid + r * 256;
        int row = s >> 3, seg = s & 7;
        cp16(sKb + row * KPCH + seg * 4,
             Kt + (size_t)row * DKL + dc * 32 + seg * 4);
    }
}

__device__ __forceinline__ void issue_v(float* sVb, const float* Vt,
                                        int ch, int tid) {
#pragma unroll
    for (int r = 0; r < 2; r++) {               // V: 8 rows x 64 f4
        int s = tid + r * 256;
        int row = s >> 6, seg = s & 63;
        cp16(sVb + row * VPCH + seg * 4,
             Vt + (size_t)(ch * 8 + row) * DKL + seg * 4);
    }
}

__global__ __launch_bounds__(256, 2) void attn_kernel(float* __restrict__ out) {
    extern __shared__ float sm[];
    float* sQ  = sm + SQ_OFF;
    float* sK  = sm + SK_OFF;
    float* sV  = sm + SV_OFF;
    float* sP  = sm + SP_OFF;
    float* sMm = sm + SMM_OFF;
    float* sLl = sm + SLL_OFF;

    const int b  = blockIdx.x >> 6;
    const int q0 = (blockIdx.x & 63) * 64;
    const float* Qg = g_Q + ((size_t)b * SQL + q0) * DKL;
    const float* Kg = g_K + (size_t)b * SKVL * DKL;
    const float* Vg = g_V + (size_t)b * SKVL * DKL;

    const int tid = threadIdx.x;
    const int txv = tid & 31;
    const int tyv = tid >> 5;

    if (tid < 64) { sMm[tid] = -1e30f; sLl[tid] = 0.f; }

    float O[8][8];
#pragma unroll
    for (int r = 0; r < 8; r++)
#pragma unroll
        for (int c = 0; c < 8; c++) O[r][c] = 0.f;

    // prologue: QK chunk 0 of tile 0 into buffer 0
    issue_qk(sQ, sK, Qg, Kg, 0, tid);
    CP_COMMIT();

    for (int t = 0; t < SKVL / 128; t++) {
        const float* Kt = Kg + (size_t)t * 128 * DKL;
        const float* Vt = Vg + (size_t)t * 128 * DKL;

        // ================= S = Q @ K^T over 8 d-chunks =================
        float S[8][4];
#pragma unroll
        for (int r = 0; r < 8; r++)
#pragma unroll
            for (int c = 0; c < 4; c++) S[r][c] = 0.f;

        for (int dc = 0; dc < 8; dc++) {
            if (dc < 7) issue_qk(sQ + ((dc + 1) & 1) * (64 * QPCH),
                                 sK + ((dc + 1) & 1) * (128 * KPCH),
                                 Qg, Kt, dc + 1, tid);
            else        issue_v(sV, Vt, 0, tid);
            CP_COMMIT();
            CP_WAIT1();
            __syncthreads();
            const float* q = sQ + (dc & 1) * (64 * QPCH);
            const float* k = sK + (dc & 1) * (128 * KPCH);
#pragma unroll
            for (int dg = 0; dg < 8; dg++) {
                float4 kf0 = *(const float4*)(k + (txv      ) * KPCH + dg * 4);
                float4 kf1 = *(const float4*)(k + (txv + 32 ) * KPCH + dg * 4);
                float4 kf2 = *(const float4*)(k + (txv + 64 ) * KPCH + dg * 4);
                float4 kf3 = *(const float4*)(k + (txv + 96 ) * KPCH + dg * 4);
#pragma unroll
                for (int r = 0; r < 8; r++) {
                    float4 qf = *(const float4*)(q + (tyv * 8 + r) * QPCH + dg * 4);
                    S[r][0] += qf.x*kf0.x + qf.y*kf0.y + qf.z*kf0.z + qf.w*kf0.w;
                    S[r][1] += qf.x*kf1.x + qf.y*kf1.y + qf.z*kf1.z + qf.w*kf1.w;
                    S[r][2] += qf.x*kf2.x + qf.y*kf2.y + qf.z*kf2.z + qf.w*kf2.w;
                    S[r][3] += qf.x*kf3.x + qf.y*kf3.y + qf.z*kf3.z + qf.w*kf3.w;
                }
            }
            __syncthreads();
        }

        // ================= online softmax (rows tyv*8+r) =================
#pragma unroll
        for (int r = 0; r < 8; r++) {
            const int row = tyv * 8 + r;
            float s0 = S[r][0] * 0.0625f;          // 1/sqrt(256)
            float s1 = S[r][1] * 0.0625f;
            float s2 = S[r][2] * 0.0625f;
            float s3 = S[r][3] * 0.0625f;
            float mloc = fmaxf(fmaxf(s0, s1), fmaxf(s2, s3));
#pragma unroll
            for (int off = 16; off > 0; off >>= 1)
                mloc = fmaxf(mloc, __shfl_xor_sync(0xffffffffu, mloc, off));
            float mold = sMm[row];
            float mn   = fmaxf(mold, mloc);
            float osc  = __expf(mold - mn);
            float p0 = __expf(s0 - mn);
            float p1 = __expf(s1 - mn);
            float p2 = __expf(s2 - mn);
            float p3 = __expf(s3 - mn);
            float ts = p0 + p1 + p2 + p3;
#pragma unroll
            for (int off = 16; off > 0; off >>= 1)
                ts += __shfl_xor_sync(0xffffffffu, ts, off);
            sLl[row] = sLl[row] * osc + ts;        // all lanes write same value
            sMm[row] = mn;
            sP[row * PPCH + txv     ] = p0;
            sP[row * PPCH + txv + 32] = p1;
            sP[row * PPCH + txv + 64] = p2;
            sP[row * PPCH + txv + 96] = p3;
#pragma unroll
            for (int c = 0; c < 8; c++) O[r][c] *= osc;
        }

        // ================= O += P @ V over 16 j-chunks =================
        for (int ch = 0; ch < 16; ch++) {
            if (ch < 15)      issue_v(sV + ((ch + 1) & 1) * (8 * VPCH), Vt, ch + 1, tid);
            else if (t < SKVL / 128 - 1)
                              issue_qk(sQ, sK, Qg, Kt + 128 * DKL, 0, tid);
            CP_COMMIT();       // empty group on final step: keeps wait math valid
            CP_WAIT1();
            __syncthreads();   // V[ch] visible; first iter also publishes sP
            const float* v    = sV + (ch & 1) * (8 * VPCH);
            const float* prow = sP + (tyv * 8) * PPCH + ch * 8;
#pragma unroll
            for (int j = 0; j < 8; j++) {
                float4 v0 = *(const float4*)(v + j * VPCH + txv * 4);
                float4 v1 = *(const float4*)(v + j * VPCH + 128 + txv * 4);
#pragma unroll
                for (int r = 0; r < 8; r++) {
                    float pv = prow[r * PPCH + j];
                    O[r][0] += pv * v0.x; O[r][1] += pv * v0.y;
                    O[r][2] += pv * v0.z; O[r][3] += pv * v0.w;
                    O[r][4] += pv * v1.x; O[r][5] += pv * v1.y;
                    O[r][6] += pv * v1.z; O[r][7] += pv * v1.w;
                }
            }
            __syncthreads();
        }
    }

    // ================= epilogue =================
#pragma unroll
    for (int r = 0; r < 8; r++) {
        const int row = tyv * 8 + r;
        float inv = 1.0f / sLl[row];
        float* orow = out + ((size_t)b * SQL + q0 + row) * DKL;
        float4 o0 = make_float4(O[r][0] * inv, O[r][1] * inv,
                                O[r][2] * inv, O[r][3] * inv);
        float4 o1 = make_float4(O[r][4] * inv, O[r][5] * inv,
                                O[r][6] * inv, O[r][7] * inv);
        *(float4*)(orow + txv * 4)       = o0;
        *(float4*)(orow + 128 + txv * 4) = o1;
    }
}

// ---------------------------------------------------------------------------
extern "C" void kernel_launch(void* const* d_in, const int* in_sizes, int n_in,
                              void* d_out, int out_size) {
    (void)in_sizes; (void)n_in; (void)out_size;
    const float* conv_local  = (const float*)d_in[0];
    const float* conv_global = (const float*)d_in[1];
    const float* Wk = (const float*)d_in[2];
    const float* bk = (const float*)d_in[3];
    const float* Wq = (const float*)d_in[4];
    const float* bq = (const float*)d_in[5];
    const float* Wv = (const float*)d_in[6];
    const float* bv = (const float*)d_in[7];
    float* out = (float*)d_out;

    void *qp, *kp, *vp;
    cudaGetSymbolAddress(&qp, g_Q);
    cudaGetSymbolAddress(&kp, g_K);
    cudaGetSymbolAddress(&vp, g_V);

    dim3 ggrid((BB * SKVL) / 64, DKL / 64);
    proj_gemm<<<ggrid, 256>>>(conv_local,  Wk, bk, (float*)kp);
    proj_gemm<<<ggrid, 256>>>(conv_local,  Wv, bv, (float*)vp);
    proj_gemm<<<ggrid, 256>>>(conv_global, Wq, bq, (float*)qp);

    const int smem = SMEM_FLOATS * (int)sizeof(float);
    cudaFuncSetAttribute(attn_kernel, cudaFuncAttributeMaxDynamicSharedMemorySize, smem);
    attn_kernel<<<BB * (SQL / 64), 256, smem>>>(out);
}